// round 6
// baseline (speedup 1.0000x reference)
#include <cuda_runtime.h>
#include <cstdint>

#define NC         100000
#define FEAT       256
#define BATCH      16384
#define F4         64                          // FEAT / 4
#define THREADS    256
#define WPB        8
#define CNT_BLOCKS (BATCH / THREADS)           // 64
#define SPW        2                           // samples per warp (MLP)
#define ACC_BLOCKS (BATCH / (WPB * SPW))       // 1024
#define CPB        256                         // classes scanned per block
#define CLS_BLOCKS ((NC + CPB - 1) / CPB)      // 391

// contrib_c = Q - 1.9602 D + 0.9801 E - (0.0199/n) ||s||^2
//   Q = sum ||x_i||^2, D = c.s, E = n ||c||^2   (t = 0.99c + 0.01 s/n)
#define A_D 1.9602f
#define A_E 0.9801f
#define A_S 0.0199f

// Scratch — zero at module load; every replay restores the all-zero invariant.
__device__ float4   g_scal[NC];                 // {Q, D, E, n}  (1.6 MB)
__device__ float4   g_sums[(size_t)NC * F4];    // rows used ONLY for n>=2 classes
__device__ float    g_loss;
__device__ unsigned g_done;

__device__ __forceinline__ void red_add_v4(float* addr, float4 v) {
    asm volatile("red.global.add.v4.f32 [%0], {%1, %2, %3, %4};"
                 :: "l"(addr), "f"(v.x), "f"(v.y), "f"(v.z), "f"(v.w)
                 : "memory");
}
__device__ __forceinline__ float dot4(float4 a, float4 b) {
    return a.x*b.x + a.y*b.y + a.z*b.z + a.w*b.w;
}

// ---------------------------------------------------------------------------
// Pass 0: per-class counts (float, exact below 2^24). Spread atomics, tiny.
// ---------------------------------------------------------------------------
__global__ __launch_bounds__(THREADS) void countk(const int* __restrict__ label) {
    int i = blockIdx.x * THREADS + threadIdx.x;
    atomicAdd(&g_scal[label[i]].w, 1.0f);
}

// ---------------------------------------------------------------------------
// Pass 1: one warp per TWO samples (8 independent 16B loads in flight per
// thread -> latency hiding). Scalar REDs into g_scal; vector RED of the x row
// into g_sums only when the class has n>=2.
// ---------------------------------------------------------------------------
__global__ __launch_bounds__(THREADS) void accum(const float* __restrict__ x,
                                                 const float* __restrict__ center,
                                                 const int* __restrict__ label) {
    int w    = (blockIdx.x * THREADS + threadIdx.x) >> 5;   // warp id
    int lane = threadIdx.x & 31;
    int sA   = w * SPW;
    int sB   = sA + 1;
    int cA   = label[sA];
    int cB   = label[sB];

    const float4* xA = reinterpret_cast<const float4*>(x)      + (size_t)sA * F4;
    const float4* xB = reinterpret_cast<const float4*>(x)      + (size_t)sB * F4;
    const float4* cAr = reinterpret_cast<const float4*>(center) + (size_t)cA * F4;
    const float4* cBr = reinterpret_cast<const float4*>(center) + (size_t)cB * F4;

    float4 a0 = xA[lane],  a1 = xA[lane + 32];
    float4 b0 = xB[lane],  b1 = xB[lane + 32];
    float4 p0 = cAr[lane], p1 = cAr[lane + 32];
    float4 q0 = cBr[lane], q1 = cBr[lane + 32];

    float qa = dot4(a0, a0) + dot4(a1, a1);
    float da = dot4(a0, p0) + dot4(a1, p1);
    float ea = dot4(p0, p0) + dot4(p1, p1);
    float qb = dot4(b0, b0) + dot4(b1, b1);
    float db = dot4(b0, q0) + dot4(b1, q1);
    float eb = dot4(q0, q0) + dot4(q1, q1);

    #pragma unroll
    for (int o = 16; o > 0; o >>= 1) {          // 6 interleaved chains
        qa += __shfl_down_sync(0xFFFFFFFFu, qa, o);
        da += __shfl_down_sync(0xFFFFFFFFu, da, o);
        ea += __shfl_down_sync(0xFFFFFFFFu, ea, o);
        qb += __shfl_down_sync(0xFFFFFFFFu, qb, o);
        db += __shfl_down_sync(0xFFFFFFFFu, db, o);
        eb += __shfl_down_sync(0xFFFFFFFFu, eb, o);
    }

    if (g_scal[cA].w >= 2.f) {                  // broadcast load
        float* srow = reinterpret_cast<float*>(g_sums + (size_t)cA * F4);
        red_add_v4(srow + lane * 4,        a0);
        red_add_v4(srow + (lane + 32) * 4, a1);
    }
    if (g_scal[cB].w >= 2.f) {
        float* srow = reinterpret_cast<float*>(g_sums + (size_t)cB * F4);
        red_add_v4(srow + lane * 4,        b0);
        red_add_v4(srow + (lane + 32) * 4, b1);
    }
    if (lane == 0) {
        atomicAdd(&g_scal[cA].x, qa);
        atomicAdd(&g_scal[cA].y, da);
        atomicAdd(&g_scal[cA].z, ea);
        atomicAdd(&g_scal[cB].x, qb);
        atomicAdd(&g_scal[cB].y, db);
        atomicAdd(&g_scal[cB].z, eb);
    }
}

// ---------------------------------------------------------------------------
// Pass 2: coalesced scan of g_scal; multi classes (n>=2) get a warp stage for
// ||s||^2 + row zeroing. Block partial -> g_loss atomic; last block writes
// the output and resets g_loss/g_done. All zero invariants restored here.
// ---------------------------------------------------------------------------
__global__ __launch_bounds__(THREADS) void classpass(float* __restrict__ out) {
    __shared__ int   s_m;
    __shared__ int   s_cls[CPB];
    __shared__ float s_n[CPB];
    __shared__ float s_wsum[WPB];
    __shared__ bool  s_last;

    int tid  = threadIdx.x;
    int lane = tid & 31;
    int wid  = tid >> 5;

    if (tid == 0) s_m = 0;
    __syncthreads();

    float contrib = 0.f;
    int c = blockIdx.x * CPB + tid;
    if (c < NC) {
        float4 sc = g_scal[c];                  // coalesced 16B
        if (sc.w > 0.f) {
            contrib = sc.x - A_D * sc.y + A_E * sc.z;
            if (sc.w == 1.f) {
                contrib -= A_S * sc.x;          // ||s||^2 == Q for n = 1
            } else {
                int p = atomicAdd(&s_m, 1);
                s_cls[p] = c;
                s_n[p]   = sc.w;
            }
            g_scal[c] = make_float4(0.f, 0.f, 0.f, 0.f);    // restore invariant
        }
    }
    __syncthreads();

    int m = s_m;                                // ~3 expected per block
    for (int i = wid; i < m; i += WPB) {
        int cc = s_cls[i];
        float4* srow = g_sums + (size_t)cc * F4;
        float4 s0 = srow[lane], s1 = srow[lane + 32];
        float4 z = make_float4(0.f, 0.f, 0.f, 0.f);
        srow[lane] = z;                         // restore invariant
        srow[lane + 32] = z;
        float ss = dot4(s0, s0) + dot4(s1, s1);
        #pragma unroll
        for (int o = 16; o > 0; o >>= 1)
            ss += __shfl_down_sync(0xFFFFFFFFu, ss, o);
        if (lane == 0) contrib -= A_S * ss / s_n[i];
    }

    #pragma unroll
    for (int o = 16; o > 0; o >>= 1)
        contrib += __shfl_down_sync(0xFFFFFFFFu, contrib, o);
    if (lane == 0) s_wsum[wid] = contrib;
    __syncthreads();

    if (tid == 0) {
        float b = 0.f;
        #pragma unroll
        for (int i = 0; i < WPB; i++) b += s_wsum[i];
        atomicAdd(&g_loss, b);                  // 391 ops on one addr: negligible
        __threadfence();
        s_last = (atomicAdd(&g_done, 1u) == (unsigned)(gridDim.x - 1));
        if (s_last) {
            out[0] = __ldcg(&g_loss) * (1.f / ((float)BATCH * (float)FEAT));
            g_loss = 0.f;                       // restore invariants
            g_done = 0u;
        }
    }
}

extern "C" void kernel_launch(void* const* d_in, const int* in_sizes, int n_in,
                              void* d_out, int out_size) {
    const float* x      = (const float*)d_in[0];   // batch_feature [16384, 256] f32
    const int*   label  = (const int*)d_in[1];     // batch_label   [16384] int32
    const float* center = (const float*)d_in[2];   // center_feature[100000, 256] f32
    float* out = (float*)d_out;

    countk   <<<CNT_BLOCKS, THREADS>>>(label);
    accum    <<<ACC_BLOCKS, THREADS>>>(x, center, label);
    classpass<<<CLS_BLOCKS, THREADS>>>(out);
}